// round 1
// baseline (speedup 1.0000x reference)
#include <cuda_runtime.h>
#include <math.h>

#define D_MODEL 1024
#define N_HEADS 16
#define DH      64
#define BATCH   2
#define SEQ     2048
#define BT      (BATCH * SEQ)      // 4096
#define D3      (3 * D_MODEL)      // 3072

// ---------------- scratch (device globals; no allocation allowed) ----------
__device__ float g_Wint[(size_t)D_MODEL * D3];        // W_in^T  [1024][3072]
__device__ float g_Woutt[(size_t)D_MODEL * D_MODEL];  // W_out^T [1024][1024]
__device__ float g_qkv[(size_t)3 * BT * D_MODEL];     // [3][B*H][T][DH]
__device__ float g_attn[(size_t)BT * D_MODEL];        // [B,T,D]

// ---------------- transpose: in[R][C] -> out[C][R] --------------------------
__global__ __launch_bounds__(256) void transpose_kernel(
    const float* __restrict__ in, float* __restrict__ out, int R, int C) {
    __shared__ float tile[32][33];
    int c0 = blockIdx.x * 32, r0 = blockIdx.y * 32;
    int tx = threadIdx.x, ty = threadIdx.y;  // 32 x 8
    #pragma unroll
    for (int i = 0; i < 32; i += 8) {
        int r = r0 + ty + i, c = c0 + tx;
        if (r < R && c < C) tile[ty + i][tx] = in[(size_t)r * C + c];
    }
    __syncthreads();
    #pragma unroll
    for (int i = 0; i < 32; i += 8) {
        int c = c0 + ty + i, r = r0 + tx;
        if (c < C && r < R) out[(size_t)c * R + r] = tile[tx][ty + i];
    }
}

// ---------------- SGEMM: C = A[M,K] @ Bt[K,N] --------------------------------
// 128x128 block tile, K-step 8, 256 threads, 8x8 micro-tile per thread.
// MODE 0: scatter into qkv layout [3][B*H][T][DH]. MODE 1: plain row-major C.
template <int MODE>
__global__ __launch_bounds__(256) void sgemm_kernel(
    const float* __restrict__ A, const float* __restrict__ Bt,
    float* __restrict__ C, int M, int N, int K) {
    __shared__ __align__(16) float As[8][128];
    __shared__ __align__(16) float Bs[8][128];

    const int tid = threadIdx.x;
    const int bm = blockIdx.y * 128;
    const int bn = blockIdx.x * 128;
    const int tx = tid & 15;
    const int ty = tid >> 4;

    const int a_row  = tid >> 1;
    const int a_col4 = (tid & 1) * 4;
    const int b_row  = tid >> 5;
    const int b_col4 = (tid & 31) * 4;

    float acc[8][8];
    #pragma unroll
    for (int i = 0; i < 8; i++)
        #pragma unroll
        for (int j = 0; j < 8; j++) acc[i][j] = 0.f;

    for (int k0 = 0; k0 < K; k0 += 8) {
        float4 av = *(const float4*)&A[(size_t)(bm + a_row) * K + k0 + a_col4];
        As[a_col4 + 0][a_row] = av.x;
        As[a_col4 + 1][a_row] = av.y;
        As[a_col4 + 2][a_row] = av.z;
        As[a_col4 + 3][a_row] = av.w;
        float4 bv = *(const float4*)&Bt[(size_t)(k0 + b_row) * N + bn + b_col4];
        *(float4*)&Bs[b_row][b_col4] = bv;
        __syncthreads();

        #pragma unroll
        for (int k = 0; k < 8; k++) {
            float4 a0 = *(const float4*)&As[k][ty * 4];
            float4 a1 = *(const float4*)&As[k][64 + ty * 4];
            float4 b0 = *(const float4*)&Bs[k][tx * 4];
            float4 b1 = *(const float4*)&Bs[k][64 + tx * 4];
            float af[8] = {a0.x, a0.y, a0.z, a0.w, a1.x, a1.y, a1.z, a1.w};
            float bf[8] = {b0.x, b0.y, b0.z, b0.w, b1.x, b1.y, b1.z, b1.w};
            #pragma unroll
            for (int i = 0; i < 8; i++)
                #pragma unroll
                for (int j = 0; j < 8; j++) acc[i][j] = fmaf(af[i], bf[j], acc[i][j]);
        }
        __syncthreads();
    }

    #pragma unroll
    for (int i = 0; i < 8; i++) {
        int m = bm + ((i < 4) ? (ty * 4 + i) : (64 + ty * 4 + i - 4));
        int b = m >> 11;          // / SEQ
        int t = m & (SEQ - 1);
        #pragma unroll
        for (int j = 0; j < 8; j++) {
            int n = bn + ((j < 4) ? (tx * 4 + j) : (64 + tx * 4 + j - 4));
            if (MODE == 0) {
                int which = n >> 10;
                int d = n & (D_MODEL - 1);
                int h = d >> 6;
                int hd = d & 63;
                size_t dst = (size_t)which * ((size_t)BT * D_MODEL) +
                             (((size_t)(b * N_HEADS + h) * SEQ + t) << 6) + hd;
                C[dst] = acc[i][j];
            } else {
                C[(size_t)m * N + n] = acc[i][j];
            }
        }
    }
}

// ---------------- causal flash attention -------------------------------------
// grid: (T/64 q-tiles, B*H). 256 threads. Q tile 64x64, K/V tiles 32x64.
__global__ __launch_bounds__(256) void attn_kernel(
    const float* __restrict__ qkv, float* __restrict__ out) {
    const int QT = 64, KT = 32;
    __shared__ float Qs[64][65];
    __shared__ float Ks[32][65];
    __shared__ __align__(16) float Vs[32][68];
    __shared__ float Ps[64][33];

    const int tid = threadIdx.x;
    const int tx = tid & 15;
    const int ty = tid >> 4;
    const int bh = blockIdx.y;
    const int q0 = blockIdx.x * QT;

    const float* Qp = qkv + ((size_t)bh * SEQ + q0) * DH;
    const float* Kp = qkv + (size_t)BT * D_MODEL + (size_t)bh * SEQ * DH;
    const float* Vp = qkv + (size_t)2 * BT * D_MODEL + (size_t)bh * SEQ * DH;

    // load Q tile (64x64)
    for (int i = tid; i < QT * DH / 4; i += 256) {
        int r = i >> 4;           // (i*4)/64
        int c = (i << 2) & 63;
        float4 v = *(const float4*)&Qp[r * DH + c];
        Qs[r][c] = v.x; Qs[r][c + 1] = v.y; Qs[r][c + 2] = v.z; Qs[r][c + 3] = v.w;
    }

    float m_r[4], l_r[4], o[4][4];
    #pragma unroll
    for (int i = 0; i < 4; i++) {
        m_r[i] = -1e30f; l_r[i] = 0.f;
        #pragma unroll
        for (int j = 0; j < 4; j++) o[i][j] = 0.f;
    }

    const float scale = 0.125f;  // 1/sqrt(64)
    const int nkt = 2 * blockIdx.x + 2;

    for (int kt = 0; kt < nkt; kt++) {
        const int k0 = kt * KT;
        __syncthreads();  // prior PV reads of Ks/Vs done before overwrite
        for (int i = tid; i < KT * DH / 4; i += 256) {
            int r = i >> 4;
            int c = (i << 2) & 63;
            float4 kv = *(const float4*)&Kp[(size_t)(k0 + r) * DH + c];
            Ks[r][c] = kv.x; Ks[r][c + 1] = kv.y; Ks[r][c + 2] = kv.z; Ks[r][c + 3] = kv.w;
            float4 vv = *(const float4*)&Vp[(size_t)(k0 + r) * DH + c];
            Vs[r][c] = vv.x; Vs[r][c + 1] = vv.y; Vs[r][c + 2] = vv.z; Vs[r][c + 3] = vv.w;
        }
        __syncthreads();

        // S = Q @ K^T : rows ty*4..+3, cols tx*2..+1
        float s[4][2] = {{0.f, 0.f}, {0.f, 0.f}, {0.f, 0.f}, {0.f, 0.f}};
        #pragma unroll 8
        for (int d = 0; d < DH; d++) {
            float qv[4], kv[2];
            #pragma unroll
            for (int i = 0; i < 4; i++) qv[i] = Qs[ty * 4 + i][d];
            #pragma unroll
            for (int j = 0; j < 2; j++) kv[j] = Ks[tx * 2 + j][d];
            #pragma unroll
            for (int i = 0; i < 4; i++)
                #pragma unroll
                for (int j = 0; j < 2; j++) s[i][j] = fmaf(qv[i], kv[j], s[i][j]);
        }

        // scale + causal mask
        #pragma unroll
        for (int i = 0; i < 4; i++) {
            int gq = q0 + ty * 4 + i;
            #pragma unroll
            for (int j = 0; j < 2; j++) {
                int gk = k0 + tx * 2 + j;
                float v = s[i][j] * scale;
                s[i][j] = (gk > gq) ? -1e30f : v;
            }
        }

        // row max across the 16 tx lanes (same ty within half-warp)
        float tmax[4];
        #pragma unroll
        for (int i = 0; i < 4; i++) tmax[i] = fmaxf(s[i][0], s[i][1]);
        #pragma unroll
        for (int off = 1; off < 16; off <<= 1)
            #pragma unroll
            for (int i = 0; i < 4; i++)
                tmax[i] = fmaxf(tmax[i], __shfl_xor_sync(0xffffffffu, tmax[i], off));

        float alpha[4], lsum[4];
        #pragma unroll
        for (int i = 0; i < 4; i++) {
            float mn = fmaxf(m_r[i], tmax[i]);
            alpha[i] = __expf(m_r[i] - mn);
            m_r[i] = mn;
            float p0 = __expf(s[i][0] - mn);
            float p1 = __expf(s[i][1] - mn);
            s[i][0] = p0; s[i][1] = p1;
            lsum[i] = p0 + p1;
        }
        #pragma unroll
        for (int off = 1; off < 16; off <<= 1)
            #pragma unroll
            for (int i = 0; i < 4; i++)
                lsum[i] += __shfl_xor_sync(0xffffffffu, lsum[i], off);
        #pragma unroll
        for (int i = 0; i < 4; i++) l_r[i] = l_r[i] * alpha[i] + lsum[i];

        // stage P, rescale O
        #pragma unroll
        for (int i = 0; i < 4; i++)
            #pragma unroll
            for (int j = 0; j < 2; j++) Ps[ty * 4 + i][tx * 2 + j] = s[i][j];
        #pragma unroll
        for (int i = 0; i < 4; i++)
            #pragma unroll
            for (int j = 0; j < 4; j++) o[i][j] *= alpha[i];
        __syncthreads();

        // O += P @ V : rows ty*4..+3, d cols tx*4..+3
        #pragma unroll 8
        for (int c = 0; c < KT; c++) {
            float pv[4];
            #pragma unroll
            for (int i = 0; i < 4; i++) pv[i] = Ps[ty * 4 + i][c];
            float4 vv = *(const float4*)&Vs[c][tx * 4];
            float vf[4] = {vv.x, vv.y, vv.z, vv.w};
            #pragma unroll
            for (int i = 0; i < 4; i++)
                #pragma unroll
                for (int j = 0; j < 4; j++) o[i][j] = fmaf(pv[i], vf[j], o[i][j]);
        }
    }

    // epilogue -> g_attn [B,T,D]
    const int b = bh / N_HEADS;
    const int h = bh % N_HEADS;
    #pragma unroll
    for (int i = 0; i < 4; i++) {
        int t = q0 + ty * 4 + i;
        float inv = 1.f / l_r[i];
        #pragma unroll
        for (int j = 0; j < 4; j++) {
            int d = tx * 4 + j;
            out[((size_t)(b * SEQ + t)) * D_MODEL + h * DH + d] = o[i][j] * inv;
        }
    }
}

// ---------------- launch ------------------------------------------------------
extern "C" void kernel_launch(void* const* d_in, const int* in_sizes, int n_in,
                              void* d_out, int out_size) {
    const float* x     = (const float*)d_in[0];
    const float* W_in  = (const float*)d_in[1];
    const float* W_out = (const float*)d_in[2];
    float* out = (float*)d_out;

    float *wint, *woutt, *qkv, *attn;
    cudaGetSymbolAddress((void**)&wint,  g_Wint);
    cudaGetSymbolAddress((void**)&woutt, g_Woutt);
    cudaGetSymbolAddress((void**)&qkv,   g_qkv);
    cudaGetSymbolAddress((void**)&attn,  g_attn);

    // 1. transpose weights -> [K][N]
    {
        dim3 thr(32, 8);
        dim3 g1(D_MODEL / 32, D3 / 32);       // W_in: R=3072, C=1024 -> out [1024][3072]
        transpose_kernel<<<g1, thr>>>(W_in, wint, D3, D_MODEL);
        dim3 g2(D_MODEL / 32, D_MODEL / 32);
        transpose_kernel<<<g2, thr>>>(W_out, woutt, D_MODEL, D_MODEL);
    }

    // 2. QKV projection, scattered into [3][B*H][T][DH]
    {
        dim3 grid(D3 / 128, BT / 128);        // (24, 32)
        sgemm_kernel<0><<<grid, 256>>>(x, wint, qkv, BT, D3, D_MODEL);
    }

    // 3. causal flash attention -> g_attn [B,T,D]
    {
        dim3 grid(SEQ / 64, BATCH * N_HEADS); // (32, 32)
        attn_kernel<<<grid, 256>>>(qkv, attn);
    }

    // 4. output projection -> d_out
    {
        dim3 grid(D_MODEL / 128, BT / 128);   // (8, 32)
        sgemm_kernel<1><<<grid, 256>>>(attn, woutt, out, BT, D_MODEL, D_MODEL);
    }
}

// round 2
// speedup vs baseline: 1.4423x; 1.4423x over previous
#include <cuda_runtime.h>
#include <math.h>

#define D_MODEL 1024
#define N_HEADS 16
#define DH      64
#define BATCH   2
#define SEQ     2048
#define BT      (BATCH * SEQ)      // 4096
#define D3      (3 * D_MODEL)      // 3072

// ---------------- scratch (device globals; no allocation allowed) ----------
__device__ float g_qkv[(size_t)3 * BT * D_MODEL];     // [3][B*H][T][DH]
__device__ float g_attn[(size_t)BT * D_MODEL];        // [B,T,D]

// ---------------- helpers ----------------------------------------------------
__device__ __forceinline__ unsigned f2tf32(float f) {
    unsigned r;
    asm("cvt.rna.tf32.f32 %0, %1;" : "=r"(r) : "f"(f));
    return r;
}

__device__ __forceinline__ void mma_tf32(
    float& c0, float& c1, float& c2, float& c3,
    unsigned a0, unsigned a1, unsigned a2, unsigned a3,
    unsigned b0, unsigned b1) {
    asm volatile(
        "mma.sync.aligned.m16n8k8.row.col.f32.tf32.tf32.f32 "
        "{%0,%1,%2,%3}, {%4,%5,%6,%7}, {%8,%9}, {%0,%1,%2,%3};"
        : "+f"(c0), "+f"(c1), "+f"(c2), "+f"(c3)
        : "r"(a0), "r"(a1), "r"(a2), "r"(a3), "r"(b0), "r"(b1));
}

// ---------------- TF32 GEMM: C[M,N] = A[M,K] @ W[N,K]^T ----------------------
// Block 128x128, k-step 32. 256 threads = 8 warps (4m x 2n), warp tile 32x64.
// MODE 0: scatter C into qkv layout [3][B*H][T][DH]. MODE 1: row-major C.
#define KSTEP 32
#define SPAD  36

template <int MODE>
__global__ __launch_bounds__(256, 2) void gemm_tf32_kernel(
    const float* __restrict__ A, const float* __restrict__ W,
    float* __restrict__ C, int M, int N, int K) {
    __shared__ __align__(16) unsigned As[128][SPAD];
    __shared__ __align__(16) unsigned Bs[128][SPAD];

    const int tid  = threadIdx.x;
    const int lane = tid & 31;
    const int wid  = tid >> 5;
    const int warp_m = wid & 3;       // 0..3 -> 32-row slice
    const int warp_n = wid >> 2;      // 0..1 -> 64-col slice
    const int bm = blockIdx.y * 128;
    const int bn = blockIdx.x * 128;

    const int lr = lane >> 2;         // 0..7
    const int lc = lane & 3;          // 0..3

    float acc[2][8][4];
    #pragma unroll
    for (int i = 0; i < 2; i++)
        #pragma unroll
        for (int j = 0; j < 8; j++)
            #pragma unroll
            for (int c = 0; c < 4; c++) acc[i][j][c] = 0.f;

    // global load indexing: 128 rows x 32 cols per tile, float4
    const int g_r = tid >> 3;         // 0..31
    const int g_q = tid & 7;          // 0..7 -> col4

    for (int k0 = 0; k0 < K; k0 += KSTEP) {
        #pragma unroll
        for (int it = 0; it < 4; it++) {
            int row = g_r + 32 * it;
            float4 av = *(const float4*)&A[(size_t)(bm + row) * K + k0 + g_q * 4];
            unsigned* dst = &As[row][g_q * 4];
            dst[0] = f2tf32(av.x); dst[1] = f2tf32(av.y);
            dst[2] = f2tf32(av.z); dst[3] = f2tf32(av.w);
            float4 bv = *(const float4*)&W[(size_t)(bn + row) * K + k0 + g_q * 4];
            unsigned* db = &Bs[row][g_q * 4];
            db[0] = f2tf32(bv.x); db[1] = f2tf32(bv.y);
            db[2] = f2tf32(bv.z); db[3] = f2tf32(bv.w);
        }
        __syncthreads();

        #pragma unroll
        for (int kk = 0; kk < KSTEP; kk += 8) {
            unsigned a[2][4];
            #pragma unroll
            for (int i = 0; i < 2; i++) {
                int m = warp_m * 32 + i * 16;
                a[i][0] = As[m + lr][kk + lc];
                a[i][1] = As[m + lr + 8][kk + lc];
                a[i][2] = As[m + lr][kk + lc + 4];
                a[i][3] = As[m + lr + 8][kk + lc + 4];
            }
            #pragma unroll
            for (int j = 0; j < 8; j++) {
                int n = warp_n * 64 + j * 8;
                unsigned b0 = Bs[n + lr][kk + lc];
                unsigned b1 = Bs[n + lr][kk + lc + 4];
                #pragma unroll
                for (int i = 0; i < 2; i++)
                    mma_tf32(acc[i][j][0], acc[i][j][1], acc[i][j][2], acc[i][j][3],
                             a[i][0], a[i][1], a[i][2], a[i][3], b0, b1);
            }
        }
        __syncthreads();
    }

    // epilogue
    #pragma unroll
    for (int i = 0; i < 2; i++) {
        #pragma unroll
        for (int j = 0; j < 8; j++) {
            #pragma unroll
            for (int c = 0; c < 4; c++) {
                int m = bm + warp_m * 32 + i * 16 + lr + ((c >= 2) ? 8 : 0);
                int n = bn + warp_n * 64 + j * 8 + 2 * lc + (c & 1);
                if (MODE == 0) {
                    int b = m >> 11;                 // / SEQ
                    int t = m & (SEQ - 1);
                    int which = n >> 10;
                    int d = n & (D_MODEL - 1);
                    int h = d >> 6;
                    int hd = d & 63;
                    size_t dst = (size_t)which * ((size_t)BT * D_MODEL) +
                                 (((size_t)(b * N_HEADS + h) * SEQ + t) << 6) + hd;
                    C[dst] = acc[i][j][c];
                } else {
                    C[(size_t)m * N + n] = acc[i][j][c];
                }
            }
        }
    }
}

// ---------------- causal flash attention (unchanged from R1) -----------------
__global__ __launch_bounds__(256) void attn_kernel(
    const float* __restrict__ qkv, float* __restrict__ out) {
    const int QT = 64, KT = 32;
    __shared__ float Qs[64][65];
    __shared__ float Ks[32][65];
    __shared__ __align__(16) float Vs[32][68];
    __shared__ float Ps[64][33];

    const int tid = threadIdx.x;
    const int tx = tid & 15;
    const int ty = tid >> 4;
    const int bh = blockIdx.y;
    const int q0 = blockIdx.x * QT;

    const float* Qp = qkv + ((size_t)bh * SEQ + q0) * DH;
    const float* Kp = qkv + (size_t)BT * D_MODEL + (size_t)bh * SEQ * DH;
    const float* Vp = qkv + (size_t)2 * BT * D_MODEL + (size_t)bh * SEQ * DH;

    for (int i = tid; i < QT * DH / 4; i += 256) {
        int r = i >> 4;
        int c = (i << 2) & 63;
        float4 v = *(const float4*)&Qp[r * DH + c];
        Qs[r][c] = v.x; Qs[r][c + 1] = v.y; Qs[r][c + 2] = v.z; Qs[r][c + 3] = v.w;
    }

    float m_r[4], l_r[4], o[4][4];
    #pragma unroll
    for (int i = 0; i < 4; i++) {
        m_r[i] = -1e30f; l_r[i] = 0.f;
        #pragma unroll
        for (int j = 0; j < 4; j++) o[i][j] = 0.f;
    }

    const float scale = 0.125f;
    const int nkt = 2 * blockIdx.x + 2;

    for (int kt = 0; kt < nkt; kt++) {
        const int k0 = kt * KT;
        __syncthreads();
        for (int i = tid; i < KT * DH / 4; i += 256) {
            int r = i >> 4;
            int c = (i << 2) & 63;
            float4 kv = *(const float4*)&Kp[(size_t)(k0 + r) * DH + c];
            Ks[r][c] = kv.x; Ks[r][c + 1] = kv.y; Ks[r][c + 2] = kv.z; Ks[r][c + 3] = kv.w;
            float4 vv = *(const float4*)&Vp[(size_t)(k0 + r) * DH + c];
            Vs[r][c] = vv.x; Vs[r][c + 1] = vv.y; Vs[r][c + 2] = vv.z; Vs[r][c + 3] = vv.w;
        }
        __syncthreads();

        float s[4][2] = {{0.f, 0.f}, {0.f, 0.f}, {0.f, 0.f}, {0.f, 0.f}};
        #pragma unroll 8
        for (int d = 0; d < DH; d++) {
            float qv[4], kv[2];
            #pragma unroll
            for (int i = 0; i < 4; i++) qv[i] = Qs[ty * 4 + i][d];
            #pragma unroll
            for (int j = 0; j < 2; j++) kv[j] = Ks[tx * 2 + j][d];
            #pragma unroll
            for (int i = 0; i < 4; i++)
                #pragma unroll
                for (int j = 0; j < 2; j++) s[i][j] = fmaf(qv[i], kv[j], s[i][j]);
        }

        #pragma unroll
        for (int i = 0; i < 4; i++) {
            int gq = q0 + ty * 4 + i;
            #pragma unroll
            for (int j = 0; j < 2; j++) {
                int gk = k0 + tx * 2 + j;
                float v = s[i][j] * scale;
                s[i][j] = (gk > gq) ? -1e30f : v;
            }
        }

        float tmax[4];
        #pragma unroll
        for (int i = 0; i < 4; i++) tmax[i] = fmaxf(s[i][0], s[i][1]);
        #pragma unroll
        for (int off = 1; off < 16; off <<= 1)
            #pragma unroll
            for (int i = 0; i < 4; i++)
                tmax[i] = fmaxf(tmax[i], __shfl_xor_sync(0xffffffffu, tmax[i], off));

        float alpha[4], lsum[4];
        #pragma unroll
        for (int i = 0; i < 4; i++) {
            float mn = fmaxf(m_r[i], tmax[i]);
            alpha[i] = __expf(m_r[i] - mn);
            m_r[i] = mn;
            float p0 = __expf(s[i][0] - mn);
            float p1 = __expf(s[i][1] - mn);
            s[i][0] = p0; s[i][1] = p1;
            lsum[i] = p0 + p1;
        }
        #pragma unroll
        for (int off = 1; off < 16; off <<= 1)
            #pragma unroll
            for (int i = 0; i < 4; i++)
                lsum[i] += __shfl_xor_sync(0xffffffffu, lsum[i], off);
        #pragma unroll
        for (int i = 0; i < 4; i++) l_r[i] = l_r[i] * alpha[i] + lsum[i];

        #pragma unroll
        for (int i = 0; i < 4; i++)
            #pragma unroll
            for (int j = 0; j < 2; j++) Ps[ty * 4 + i][tx * 2 + j] = s[i][j];
        #pragma unroll
        for (int i = 0; i < 4; i++)
            #pragma unroll
            for (int j = 0; j < 4; j++) o[i][j] *= alpha[i];
        __syncthreads();

        #pragma unroll 8
        for (int c = 0; c < KT; c++) {
            float pv[4];
            #pragma unroll
            for (int i = 0; i < 4; i++) pv[i] = Ps[ty * 4 + i][c];
            float4 vv = *(const float4*)&Vs[c][tx * 4];
            float vf[4] = {vv.x, vv.y, vv.z, vv.w};
            #pragma unroll
            for (int i = 0; i < 4; i++)
                #pragma unroll
                for (int j = 0; j < 4; j++) o[i][j] = fmaf(pv[i], vf[j], o[i][j]);
        }
    }

    const int b = bh / N_HEADS;
    const int h = bh % N_HEADS;
    #pragma unroll
    for (int i = 0; i < 4; i++) {
        int t = q0 + ty * 4 + i;
        float inv = 1.f / l_r[i];
        #pragma unroll
        for (int j = 0; j < 4; j++) {
            int d = tx * 4 + j;
            out[((size_t)(b * SEQ + t)) * D_MODEL + h * DH + d] = o[i][j] * inv;
        }
    }
}

// ---------------- launch ------------------------------------------------------
extern "C" void kernel_launch(void* const* d_in, const int* in_sizes, int n_in,
                              void* d_out, int out_size) {
    const float* x     = (const float*)d_in[0];
    const float* W_in  = (const float*)d_in[1];
    const float* W_out = (const float*)d_in[2];
    float* out = (float*)d_out;

    float *qkv, *attn;
    cudaGetSymbolAddress((void**)&qkv,  g_qkv);
    cudaGetSymbolAddress((void**)&attn, g_attn);

    // 1. QKV projection (TF32 tensor cores), scattered into [3][B*H][T][DH]
    {
        dim3 grid(D3 / 128, BT / 128);        // (24, 32)
        gemm_tf32_kernel<0><<<grid, 256>>>(x, W_in, qkv, BT, D3, D_MODEL);
    }

    // 2. causal flash attention -> g_attn [B,T,D]
    {
        dim3 grid(SEQ / 64, BATCH * N_HEADS); // (32, 32)
        attn_kernel<<<grid, 256>>>(qkv, attn);
    }

    // 3. output projection (TF32 tensor cores) -> d_out
    {
        dim3 grid(D_MODEL / 128, BT / 128);   // (8, 32)
        gemm_tf32_kernel<1><<<grid, 256>>>(attn, W_out, out, BT, D_MODEL, D_MODEL);
    }
}

// round 3
// speedup vs baseline: 2.9846x; 2.0694x over previous
#include <cuda_runtime.h>
#include <math.h>

#define D_MODEL 1024
#define N_HEADS 16
#define DH      64
#define BATCH   2
#define SEQ     2048
#define BT      (BATCH * SEQ)      // 4096
#define D3      (3 * D_MODEL)      // 3072

// ---------------- scratch (device globals; no allocation allowed) ----------
__device__ float g_qkv[(size_t)3 * BT * D_MODEL];     // [3][B*H][T][DH]
__device__ float g_attn[(size_t)BT * D_MODEL];        // [B,T,D]

// ---------------- helpers ----------------------------------------------------
__device__ __forceinline__ unsigned f2tf32(float f) {
    unsigned r;
    asm("cvt.rna.tf32.f32 %0, %1;" : "=r"(r) : "f"(f));
    return r;
}

__device__ __forceinline__ void mma_tf32(
    float& c0, float& c1, float& c2, float& c3,
    unsigned a0, unsigned a1, unsigned a2, unsigned a3,
    unsigned b0, unsigned b1) {
    asm volatile(
        "mma.sync.aligned.m16n8k8.row.col.f32.tf32.tf32.f32 "
        "{%0,%1,%2,%3}, {%4,%5,%6,%7}, {%8,%9}, {%0,%1,%2,%3};"
        : "+f"(c0), "+f"(c1), "+f"(c2), "+f"(c3)
        : "r"(a0), "r"(a1), "r"(a2), "r"(a3), "r"(b0), "r"(b1));
}

// ---------------- TF32 GEMM: C[M,N] = A[M,K] @ W[N,K]^T ----------------------
#define KSTEP 32
#define SPAD  36

template <int MODE>
__global__ __launch_bounds__(256, 2) void gemm_tf32_kernel(
    const float* __restrict__ A, const float* __restrict__ W,
    float* __restrict__ C, int M, int N, int K) {
    __shared__ __align__(16) unsigned As[128][SPAD];
    __shared__ __align__(16) unsigned Bs[128][SPAD];

    const int tid  = threadIdx.x;
    const int lane = tid & 31;
    const int wid  = tid >> 5;
    const int warp_m = wid & 3;
    const int warp_n = wid >> 2;
    const int bm = blockIdx.y * 128;
    const int bn = blockIdx.x * 128;

    const int lr = lane >> 2;
    const int lc = lane & 3;

    float acc[2][8][4];
    #pragma unroll
    for (int i = 0; i < 2; i++)
        #pragma unroll
        for (int j = 0; j < 8; j++)
            #pragma unroll
            for (int c = 0; c < 4; c++) acc[i][j][c] = 0.f;

    const int g_r = tid >> 3;
    const int g_q = tid & 7;

    for (int k0 = 0; k0 < K; k0 += KSTEP) {
        #pragma unroll
        for (int it = 0; it < 4; it++) {
            int row = g_r + 32 * it;
            float4 av = *(const float4*)&A[(size_t)(bm + row) * K + k0 + g_q * 4];
            unsigned* dst = &As[row][g_q * 4];
            dst[0] = f2tf32(av.x); dst[1] = f2tf32(av.y);
            dst[2] = f2tf32(av.z); dst[3] = f2tf32(av.w);
            float4 bv = *(const float4*)&W[(size_t)(bn + row) * K + k0 + g_q * 4];
            unsigned* db = &Bs[row][g_q * 4];
            db[0] = f2tf32(bv.x); db[1] = f2tf32(bv.y);
            db[2] = f2tf32(bv.z); db[3] = f2tf32(bv.w);
        }
        __syncthreads();

        #pragma unroll
        for (int kk = 0; kk < KSTEP; kk += 8) {
            unsigned a[2][4];
            #pragma unroll
            for (int i = 0; i < 2; i++) {
                int m = warp_m * 32 + i * 16;
                a[i][0] = As[m + lr][kk + lc];
                a[i][1] = As[m + lr + 8][kk + lc];
                a[i][2] = As[m + lr][kk + lc + 4];
                a[i][3] = As[m + lr + 8][kk + lc + 4];
            }
            #pragma unroll
            for (int j = 0; j < 8; j++) {
                int n = warp_n * 64 + j * 8;
                unsigned b0 = Bs[n + lr][kk + lc];
                unsigned b1 = Bs[n + lr][kk + lc + 4];
                #pragma unroll
                for (int i = 0; i < 2; i++)
                    mma_tf32(acc[i][j][0], acc[i][j][1], acc[i][j][2], acc[i][j][3],
                             a[i][0], a[i][1], a[i][2], a[i][3], b0, b1);
            }
        }
        __syncthreads();
    }

    #pragma unroll
    for (int i = 0; i < 2; i++) {
        #pragma unroll
        for (int j = 0; j < 8; j++) {
            #pragma unroll
            for (int c = 0; c < 4; c++) {
                int m = bm + warp_m * 32 + i * 16 + lr + ((c >= 2) ? 8 : 0);
                int n = bn + warp_n * 64 + j * 8 + 2 * lc + (c & 1);
                if (MODE == 0) {
                    int b = m >> 11;
                    int t = m & (SEQ - 1);
                    int which = n >> 10;
                    int d = n & (D_MODEL - 1);
                    int h = d >> 6;
                    int hd = d & 63;
                    size_t dst = (size_t)which * ((size_t)BT * D_MODEL) +
                                 (((size_t)(b * N_HEADS + h) * SEQ + t) << 6) + hd;
                    C[dst] = acc[i][j][c];
                } else {
                    C[(size_t)m * N + n] = acc[i][j][c];
                }
            }
        }
    }
}

// ---------------- TF32 tensor-core causal flash attention --------------------
// Block: 128 Q rows, 8 warps (16 rows each). K/V tiles 64x64 in SMEM.
// grid: (SEQ/128, B*H). Q held in registers as tf32 fragments (pre-scaled).
#define QT 128
#define KT 64
#define KS_PAD 68
#define VS_PAD 72

__global__ __launch_bounds__(256) void attn_mma_kernel(
    const float* __restrict__ qkv, float* __restrict__ out) {
    __shared__ __align__(16) unsigned Ks[KT][KS_PAD];
    __shared__ __align__(16) unsigned Vs[KT][VS_PAD];

    const int tid  = threadIdx.x;
    const int lane = tid & 31;
    const int wid  = tid >> 5;
    const int lr = lane >> 2;
    const int lc = lane & 3;

    const int bh = blockIdx.y;
    const int qt = (gridDim.x - 1) - blockIdx.x;   // heavy tiles first
    const int q0 = qt * QT;

    const float* Qp = qkv + ((size_t)bh * SEQ + q0) * DH;
    const float* Kp = qkv + (size_t)BT * D_MODEL + (size_t)bh * SEQ * DH;
    const float* Vp = qkv + (size_t)2 * BT * D_MODEL + (size_t)bh * SEQ * DH;

    // ---- load Q fragments into registers (scaled by 1/8, exact in tf32) ----
    unsigned qa[8][4];
    {
        const int r0 = wid * 16 + lr;
        #pragma unroll
        for (int kk = 0; kk < 8; kk++) {
            int c = kk * 8 + lc;
            qa[kk][0] = f2tf32(0.125f * Qp[(size_t)r0 * DH + c]);
            qa[kk][1] = f2tf32(0.125f * Qp[(size_t)(r0 + 8) * DH + c]);
            qa[kk][2] = f2tf32(0.125f * Qp[(size_t)r0 * DH + c + 4]);
            qa[kk][3] = f2tf32(0.125f * Qp[(size_t)(r0 + 8) * DH + c + 4]);
        }
    }

    float o[8][4];
    #pragma unroll
    for (int n = 0; n < 8; n++)
        #pragma unroll
        for (int c = 0; c < 4; c++) o[n][c] = 0.f;
    float m0 = -1e30f, m1 = -1e30f, l0 = 0.f, l1 = 0.f;

    const int nkt = 2 * qt + 2;
    const int row0 = q0 + wid * 16 + lr;   // global q row for c0/c1
    const int row1 = row0 + 8;             // global q row for c2/c3

    for (int kt = 0; kt < nkt; kt++) {
        const int k0 = kt * KT;
        __syncthreads();
        // ---- cooperative K/V tile load, converted to tf32 ----
        #pragma unroll
        for (int it = 0; it < 4; it++) {
            int i = tid + 256 * it;
            int r = i >> 4;
            int c = (i & 15) * 4;
            float4 kv = *(const float4*)&Kp[(size_t)(k0 + r) * DH + c];
            *(uint4*)&Ks[r][c] = make_uint4(f2tf32(kv.x), f2tf32(kv.y),
                                            f2tf32(kv.z), f2tf32(kv.w));
            float4 vv = *(const float4*)&Vp[(size_t)(k0 + r) * DH + c];
            *(uint4*)&Vs[r][c] = make_uint4(f2tf32(vv.x), f2tf32(vv.y),
                                            f2tf32(vv.z), f2tf32(vv.w));
        }
        __syncthreads();

        // ---- S = (Q/8) @ K^T : per warp 16 x 64 ----
        float s[8][4];
        #pragma unroll
        for (int n = 0; n < 8; n++)
            #pragma unroll
            for (int c = 0; c < 4; c++) s[n][c] = 0.f;

        #pragma unroll
        for (int n = 0; n < 8; n++) {
            #pragma unroll
            for (int kk = 0; kk < 8; kk++) {
                unsigned b0 = Ks[n * 8 + lr][kk * 8 + lc];
                unsigned b1 = Ks[n * 8 + lr][kk * 8 + lc + 4];
                mma_tf32(s[n][0], s[n][1], s[n][2], s[n][3],
                         qa[kk][0], qa[kk][1], qa[kk][2], qa[kk][3], b0, b1);
            }
        }

        // ---- causal mask (only needed on the last two tiles) ----
        if (kt >= 2 * qt) {
            #pragma unroll
            for (int n = 0; n < 8; n++) {
                int col0 = k0 + n * 8 + 2 * lc;
                if (col0 > row0)     s[n][0] = -1e30f;
                if (col0 + 1 > row0) s[n][1] = -1e30f;
                if (col0 > row1)     s[n][2] = -1e30f;
                if (col0 + 1 > row1) s[n][3] = -1e30f;
            }
        }

        // ---- online softmax (rows lr and lr+8) ----
        float mx0 = -1e30f, mx1 = -1e30f;
        #pragma unroll
        for (int n = 0; n < 8; n++) {
            mx0 = fmaxf(mx0, fmaxf(s[n][0], s[n][1]));
            mx1 = fmaxf(mx1, fmaxf(s[n][2], s[n][3]));
        }
        mx0 = fmaxf(mx0, __shfl_xor_sync(0xffffffffu, mx0, 1));
        mx0 = fmaxf(mx0, __shfl_xor_sync(0xffffffffu, mx0, 2));
        mx1 = fmaxf(mx1, __shfl_xor_sync(0xffffffffu, mx1, 1));
        mx1 = fmaxf(mx1, __shfl_xor_sync(0xffffffffu, mx1, 2));

        float mn0 = fmaxf(m0, mx0), mn1 = fmaxf(m1, mx1);
        float alpha0 = __expf(m0 - mn0), alpha1 = __expf(m1 - mn1);
        m0 = mn0; m1 = mn1;

        float sum0 = 0.f, sum1 = 0.f;
        #pragma unroll
        for (int n = 0; n < 8; n++) {
            s[n][0] = __expf(s[n][0] - mn0);
            s[n][1] = __expf(s[n][1] - mn0);
            s[n][2] = __expf(s[n][2] - mn1);
            s[n][3] = __expf(s[n][3] - mn1);
            sum0 += s[n][0] + s[n][1];
            sum1 += s[n][2] + s[n][3];
        }
        sum0 += __shfl_xor_sync(0xffffffffu, sum0, 1);
        sum0 += __shfl_xor_sync(0xffffffffu, sum0, 2);
        sum1 += __shfl_xor_sync(0xffffffffu, sum1, 1);
        sum1 += __shfl_xor_sync(0xffffffffu, sum1, 2);
        l0 = l0 * alpha0 + sum0;
        l1 = l1 * alpha1 + sum1;

        // ---- rescale O ----
        #pragma unroll
        for (int n = 0; n < 8; n++) {
            o[n][0] *= alpha0; o[n][1] *= alpha0;
            o[n][2] *= alpha1; o[n][3] *= alpha1;
        }

        // ---- transpose P accum layout -> A-operand layout (quad shuffles) ---
        // accum: (lr, 2lc),(lr, 2lc+1),(lr+8, 2lc),(lr+8, 2lc+1)
        // A:     (lr, lc), (lr+8, lc), (lr, lc+4), (lr+8, lc+4)
        const int qbase = lane & ~3;
        const int h0 = qbase + (lc >> 1);
        const int h1 = h0 + 2;
        const bool odd = lc & 1;
        #pragma unroll
        for (int n = 0; n < 8; n++) {
            float t0 = __shfl_sync(0xffffffffu, s[n][0], h0);
            float t1 = __shfl_sync(0xffffffffu, s[n][1], h0);
            float u0 = __shfl_sync(0xffffffffu, s[n][0], h1);
            float u1 = __shfl_sync(0xffffffffu, s[n][1], h1);
            float v0 = __shfl_sync(0xffffffffu, s[n][2], h0);
            float v1 = __shfl_sync(0xffffffffu, s[n][3], h0);
            float w0 = __shfl_sync(0xffffffffu, s[n][2], h1);
            float w1 = __shfl_sync(0xffffffffu, s[n][3], h1);
            s[n][0] = __uint_as_float(f2tf32(odd ? t1 : t0));  // (lr, lc)
            s[n][1] = __uint_as_float(f2tf32(odd ? v1 : v0));  // (lr+8, lc)
            s[n][2] = __uint_as_float(f2tf32(odd ? u1 : u0));  // (lr, lc+4)
            s[n][3] = __uint_as_float(f2tf32(odd ? w1 : w0));  // (lr+8, lc+4)
        }

        // ---- O += P @ V ----
        #pragma unroll
        for (int d = 0; d < 8; d++) {
            #pragma unroll
            for (int kk = 0; kk < 8; kk++) {
                unsigned b0 = Vs[kk * 8 + lc][d * 8 + lr];
                unsigned b1 = Vs[kk * 8 + lc + 4][d * 8 + lr];
                mma_tf32(o[d][0], o[d][1], o[d][2], o[d][3],
                         __float_as_uint(s[kk][0]), __float_as_uint(s[kk][1]),
                         __float_as_uint(s[kk][2]), __float_as_uint(s[kk][3]),
                         b0, b1);
            }
        }
    }

    // ---- epilogue: normalize and store to g_attn [B,T,D] ----
    const int b = bh >> 4;
    const int h = bh & 15;
    const float inv0 = 1.f / l0;
    const float inv1 = 1.f / l1;
    #pragma unroll
    for (int n = 0; n < 8; n++) {
        int d = h * DH + n * 8 + 2 * lc;
        float2 r0v = make_float2(o[n][0] * inv0, o[n][1] * inv0);
        float2 r1v = make_float2(o[n][2] * inv1, o[n][3] * inv1);
        *(float2*)&out[((size_t)(b * SEQ + row0)) * D_MODEL + d] = r0v;
        *(float2*)&out[((size_t)(b * SEQ + row1)) * D_MODEL + d] = r1v;
    }
}

// ---------------- launch ------------------------------------------------------
extern "C" void kernel_launch(void* const* d_in, const int* in_sizes, int n_in,
                              void* d_out, int out_size) {
    const float* x     = (const float*)d_in[0];
    const float* W_in  = (const float*)d_in[1];
    const float* W_out = (const float*)d_in[2];
    float* out = (float*)d_out;

    float *qkv, *attn;
    cudaGetSymbolAddress((void**)&qkv,  g_qkv);
    cudaGetSymbolAddress((void**)&attn, g_attn);

    // 1. QKV projection (TF32 mma), scattered into [3][B*H][T][DH]
    {
        dim3 grid(D3 / 128, BT / 128);
        gemm_tf32_kernel<0><<<grid, 256>>>(x, W_in, qkv, BT, D3, D_MODEL);
    }

    // 2. causal flash attention (TF32 mma) -> g_attn [B,T,D]
    {
        dim3 grid(SEQ / QT, BATCH * N_HEADS);  // (16, 32)
        attn_mma_kernel<<<grid, 256>>>(qkv, attn);
    }

    // 3. output projection (TF32 mma) -> d_out
    {
        dim3 grid(D_MODEL / 128, BT / 128);
        gemm_tf32_kernel<1><<<grid, 256>>>(attn, W_out, out, BT, D_MODEL, D_MODEL);
    }
}